// round 7
// baseline (speedup 1.0000x reference)
#include <cuda_runtime.h>
#include <math.h>

#define N_NODES 200
#define NM1     199
#define E_TOT   39800

typedef unsigned long long u64;

__device__ __forceinline__ u64 pack2(float lo, float hi) {
    u64 r; asm("mov.b64 %0,{%1,%2};" : "=l"(r) : "f"(lo), "f"(hi)); return r;
}
__device__ __forceinline__ void unpack2(u64 v, float& lo, float& hi) {
    asm("mov.b64 {%0,%1},%2;" : "=f"(lo), "=f"(hi) : "l"(v));
}
__device__ __forceinline__ void ffma2(u64& d, u64 a, u64 b) {
    asm("fma.rn.f32x2 %0,%1,%2,%0;" : "+l"(d) : "l"(a), "l"(b));
}

// ---------------- scratch ----------------
__device__ __align__(16) float g_part[16 * 200 * 512];
__device__ __align__(16) float g_wgp [4 * 257 * 512];
__device__ __align__(16) float g_h1[200 * 512];
__device__ __align__(16) float g_h2[200 * 256];
__device__ __align__(16) float g_Gt[200 * 512];      // [n][o*128+h]  (transposed!)
__device__ __align__(16) float g_c [200 * 4];
__device__ __align__(16) float g_P [200 * 4];
__device__ __align__(16) float g_msg[E_TOT * 4];
__device__ __align__(16) float g_W3G [257 * 512];    // [h*4+o] cols; row 256 = bias
__device__ __align__(16) float g_W3CH[257 * 12];
__device__ __align__(16) float g_Ae[200 * 256];
__device__ __align__(16) float g_Be[200 * 256];
__device__ __align__(16) float g_w3b3[257 * 1024];
__device__ __align__(16) float g_wp2p[1024 * 512];

// ---------------- 256-thread GEMM tile: 16 rows x 128 cols ----------------
__device__ void gemm_tile(const float* __restrict__ A, int lda,
                          const float* __restrict__ B, int ldb,
                          float* __restrict__ outp, int ldo, int M,
                          int col0, int row0, int k0, int k1,
                          const float* __restrict__ bias, float* sh, int modeGt) {
    float* As = sh;          // [16k][16m]
    float* Bs = sh + 256;    // [16k][128n]
    int t = threadIdx.x;
    int tx = t & 31, ty = t >> 5;
    u64 acc[4];
#pragma unroll
    for (int c = 0; c < 4; c++) acc[c] = pack2(0.f, 0.f);
    int am = t >> 4, ak = t & 15;
    int bk = t >> 4, bn = (t & 15) * 8;
    unsigned sa = (unsigned)__cvta_generic_to_shared(As + ty * 2);

    for (int kt = k0; kt < k1; kt += 16) {
        {
            int gr = row0 + am;
            float av = (gr < M) ? A[(size_t)gr * lda + kt + ak] : 0.f;
            As[ak * 16 + am] = av;
        }
        {
            const float4* bp = (const float4*)(B + (size_t)(kt + bk) * ldb + col0 + bn);
            *(float4*)(Bs + bk * 128 + bn)     = bp[0];
            *(float4*)(Bs + bk * 128 + bn + 4) = bp[1];
        }
        __syncthreads();
#pragma unroll
        for (int kk = 0; kk < 16; kk++) {
            u64 ap;
            asm("ld.shared.u64 %0,[%1];" : "=l"(ap) : "r"(sa + kk * 64));
            float4 b4 = *(float4*)(Bs + kk * 128 + tx * 4);
            ffma2(acc[0], ap, pack2(b4.x, b4.x));
            ffma2(acc[1], ap, pack2(b4.y, b4.y));
            ffma2(acc[2], ap, pack2(b4.z, b4.z));
            ffma2(acc[3], ap, pack2(b4.w, b4.w));
        }
        __syncthreads();
    }
    int gr0 = row0 + ty * 2, gr1 = gr0 + 1;
#pragma unroll
    for (int c = 0; c < 4; c++) {
        float lo, hi; unpack2(acc[c], lo, hi);
        int col = col0 + tx * 4 + c;
        float bv = bias ? bias[col] : 0.f;
        lo += bv; hi += bv;
        int oc = modeGt ? ((col & 3) * 128 + (col >> 2)) : col;
        if (gr0 < M) outp[(size_t)gr0 * ldo + oc] = lo;
        if (gr1 < M) outp[(size_t)gr1 * ldo + oc] = hi;
    }
}

// ======== K1: gemm1 partials | permute wp2 | prep | W3CH | w3b3 copy ========
__global__ void k_p0(const float* __restrict__ roi,  const float* __restrict__ w1,
                     const float* __restrict__ w3,   const float* __restrict__ b3,
                     const float* __restrict__ wp2,  const float* __restrict__ bp2,
                     const float* __restrict__ wi,   const float* __restrict__ rootw,
                     const float* __restrict__ bbox, const float* __restrict__ dirs,
                     const float* __restrict__ we1,  const float* __restrict__ be1) {
    __shared__ __align__(16) float sh[3072];
    int task = blockIdx.x, t = threadIdx.x;
    if (task < 832) {
        int col0 = (task & 3) * 128;
        int row0 = ((task >> 2) % 13) * 16;
        int z = task / 52;
        gemm_tile(roi, 2048, w1, 512, g_part + (size_t)z * 102400, 512,
                  N_NODES, col0, row0, z * 128, z * 128 + 128, nullptr, sh, 0);
    } else if (task < 1856) {
        int base = (task - 832) * 512;
#pragma unroll
        for (int q = 0; q < 2; q++) {
            int idx = base + t + q * 256;
            int i = idx >> 9, r = idx & 511;
            g_wp2p[idx] = wp2[(size_t)(r >> 2) * 4096 + i * 4 + (r & 3)];
        }
    } else if (task < 2056) {
        int n = task - 1856;
        float attr[8];
#pragma unroll
        for (int k = 0; k < 4; k++) attr[k] = bbox[n * 4 + k] * (1.0f / 1024.0f);
#pragma unroll
        for (int k = 0; k < 4; k++) attr[4 + k] = dirs[n * 4 + k];
        int u = t;
        float a = be1[u], b = 0.f;
#pragma unroll
        for (int k = 0; k < 8; k++) {
            a += attr[k] * we1[k * 256 + u];
            b += attr[k] * we1[(8 + k) * 256 + u];
        }
        g_Ae[n * 256 + u] = a;
        g_Be[n * 256 + u] = b;
    } else if (task < 2313) {
        int gr = task - 2056;
        float acc[12];
#pragma unroll
        for (int c = 0; c < 12; c++) acc[c] = 0.f;
        for (int i = t; i < 1024; i += 256) {
            float a = (gr < 256) ? w3[(size_t)gr * 1024 + i] : b3[i];
            float4 p = *(const float4*)(bp2 + i * 4);
            float4 q = *(const float4*)(wi + i * 4);
            float4 r = *(const float4*)(rootw + i * 4);
            acc[0] += a * p.x; acc[1] += a * p.y; acc[2]  += a * p.z; acc[3]  += a * p.w;
            acc[4] += a * q.x; acc[5] += a * q.y; acc[6]  += a * q.z; acc[7]  += a * q.w;
            acc[8] += a * r.x; acc[9] += a * r.y; acc[10] += a * r.z; acc[11] += a * r.w;
        }
#pragma unroll
        for (int c = 0; c < 12; c++) sh[t * 12 + c] = acc[c];
        __syncthreads();
        for (int s = 128; s > 0; s >>= 1) {
            if (t < s)
#pragma unroll
                for (int c = 0; c < 12; c++) sh[t * 12 + c] += sh[(t + s) * 12 + c];
            __syncthreads();
        }
        if (t < 12) g_W3CH[gr * 12 + t] = sh[t];
    } else {
        int idx = (task - 2313) * 256 + t;
        if (idx < 257 * 1024) {
            int row = idx >> 10, col = idx & 1023;
            g_w3b3[idx] = (row < 256) ? w3[(size_t)row * 1024 + col] : b3[col];
        }
    }
}

// ======== K2: h1 reduce | W3G split-K partials ========
__global__ void k_p1(const float* __restrict__ b1) {
    __shared__ __align__(16) float sh[2304];
    int task = blockIdx.x, t = threadIdx.x;
    if (task < 400) {
        int idx = task * 256 + t;
        float s = 0.f;
#pragma unroll
        for (int z = 0; z < 16; z++) s += g_part[(size_t)z * 102400 + idx];
        g_h1[idx] = fmaxf(s + b1[idx & 511], 0.f);
    } else {
        int w = task - 400;
        int col0 = (w & 3) * 128;
        int row0 = ((w >> 2) % 17) * 16;
        int z = w / 68;
        gemm_tile(g_w3b3, 1024, g_wp2p, 512, g_wgp + (size_t)z * 131584, 512,
                  257, col0, row0, z * 256, z * 256 + 256, nullptr, sh, 0);
    }
}

// ======== K3: gemm2 partials | W3G reduce ========
__global__ void k_p2(const float* __restrict__ w2) {
    __shared__ __align__(16) float sh[2304];
    int task = blockIdx.x, t = threadIdx.x;
    if (task < 208) {
        int col0 = (task & 1) * 128;
        int row0 = ((task >> 1) % 13) * 16;
        int z = task / 26;
        gemm_tile(g_h1, 512, w2, 256, g_part + (size_t)z * 51200, 256,
                  N_NODES, col0, row0, z * 64, z * 64 + 64, nullptr, sh, 0);
    } else {
        int idx = (task - 208) * 256 + t;
        if (idx < 257 * 512) {
            float s = 0.f;
#pragma unroll
            for (int z = 0; z < 4; z++) s += g_wgp[(size_t)z * 131584 + idx];
            g_W3G[idx] = s;
        }
    }
}

// ======== K4: h2 reduce ========
__global__ void k_p3(const float* __restrict__ b2) {
    int idx = blockIdx.x * 256 + threadIdx.x;
    float s = 0.f;
#pragma unroll
    for (int z = 0; z < 8; z++) s += g_part[(size_t)z * 51200 + idx];
    g_h2[idx] = fmaxf(s + b2[idx & 255], 0.f);
}

// ======== K5: Gt = (h2 @ W3G + bias) transposed | heads ========
__global__ void k_p4(const float* __restrict__ bi, float* __restrict__ out2) {
    __shared__ __align__(16) float sh[3072];
    int task = blockIdx.x, t = threadIdx.x;
    if (task < 52) {
        int col0 = (task & 3) * 128;
        int row0 = (task >> 2) * 16;
        gemm_tile(g_h2, 256, g_W3G, 512, g_Gt, 512, N_NODES,
                  col0, row0, 0, 256, g_W3G + 256 * 512, sh, 1);
    } else {
        int n = task - 52;
        float a = g_h2[n * 256 + t];
        float4 w0  = *(const float4*)(g_W3CH + t * 12);
        float4 w1v = *(const float4*)(g_W3CH + t * 12 + 4);
        float4 w2v = *(const float4*)(g_W3CH + t * 12 + 8);
        float acc[12] = {a*w0.x, a*w0.y, a*w0.z, a*w0.w,
                         a*w1v.x, a*w1v.y, a*w1v.z, a*w1v.w,
                         a*w2v.x, a*w2v.y, a*w2v.z, a*w2v.w};
#pragma unroll
        for (int q = 0; q < 12; q++) sh[t * 12 + q] = acc[q];
        __syncthreads();
        for (int s = 128; s > 0; s >>= 1) {
            if (t < s)
#pragma unroll
                for (int q = 0; q < 12; q++) sh[t * 12 + q] += sh[(t + s) * 12 + q];
            __syncthreads();
        }
        if (t == 0) {
#pragma unroll
            for (int o = 0; o < 4; o++) {
                g_c[n * 4 + o] = sh[o] + g_W3CH[256 * 12 + o];
                float cv = sh[4 + o] + g_W3CH[256 * 12 + 4 + o] + bi[o];
                out2[n * 4 + o] = 1.f / (1.f + expf(-cv));
                g_P[n * 4 + o] = sh[8 + o] + g_W3CH[256 * 12 + 8 + o];
            }
        }
    }
}

// ======== K6: edge kernel (vectorized LSU) ========
__global__ void k_edge(const float* __restrict__ pri,
                       const float* __restrict__ we2, const float* __restrict__ be2,
                       const float* __restrict__ we3, const float* __restrict__ be3,
                       const float* __restrict__ wp1, const float* __restrict__ bp1,
                       float* __restrict__ edge_out) {
    // sbuf: h1 chunk [64u][68e] (4352) + we2 chunk [64u][64v] (4096) = 8448
    //       later: h2 flat [e*64+v] (4096)   later: heh [e*132+h] (8448)
    __shared__ __align__(16) float sbuf[8448];
    __shared__ __align__(16) float s_G[1024];
    __shared__ __align__(16) float s_A[512];
    __shared__ __align__(16) float s_we3t[192];   // [w*64+v]
    __shared__ float s_e4[256];
    __shared__ int s_src[64], s_dst[64];

    int t = threadIdx.x;
    int base = blockIdx.x * 64;
    int src0 = base / NM1;
    int last = min(base + 63, E_TOT - 1);
    int src1 = last / NM1;

    if (t < 64) {
        int ge = base + t;
        int i = src0, j = 0;
        if (ge < E_TOT) {
            i = ge / NM1;
            int r = ge - i * NM1;
            j = (r < i) ? r : r + 1;
        }
        s_src[t] = i; s_dst[t] = j;
    }
    if (t < 128) {  // stage A rows (float4)
        int row = t >> 6, k4 = (t & 63) * 4;
        *(float4*)(s_A + row * 256 + k4) =
            *(const float4*)(g_Ae + (row ? src1 : src0) * 256 + k4);
    }
    if (t < 192) s_we3t[t] = we3[(t & 63) * 3 + (t >> 6)];
    __syncthreads();

    // ---- layer2: [64e,256u]@[256u,64v], K in 4 chunks of 64 ----
    int e0 = (t >> 4) * 4;
    int v0 = (t & 15) * 4;
    u64 acc01[4], acc23[4];
#pragma unroll
    for (int cq = 0; cq < 4; cq++) {
        float b = be2[v0 + cq];
        acc01[cq] = pack2(b, b);
        acc23[cq] = pack2(b, b);
    }
    unsigned h1base = (unsigned)__cvta_generic_to_shared(sbuf + e0);

    for (int uc = 0; uc < 4; uc++) {
        // h1 chunk build: quad-vectorized. quad idx: e = q>>4, jj0 = (q&15)*4
#pragma unroll
        for (int k = 0; k < 4; k++) {
            int q = t + k * 256;
            int e = q >> 4, jj0 = (q & 15) * 4;
            int u0 = uc * 64 + jj0;
            float4 bv = *(const float4*)(g_Be + s_dst[e] * 256 + u0);
            int aoff = (s_src[e] == src0) ? 0 : 256;
            float4 av = *(const float4*)(s_A + aoff + u0);
            int ge = base + e;
            float h0 = 0.f, h1v = 0.f, h2v = 0.f, h3 = 0.f;
            if (ge < E_TOT) {
                h0 = fmaxf(av.x + bv.x, 0.f);
                h1v = fmaxf(av.y + bv.y, 0.f);
                h2v = fmaxf(av.z + bv.z, 0.f);
                h3 = fmaxf(av.w + bv.w, 0.f);
            }
            sbuf[(jj0 + 0) * 68 + e] = h0;
            sbuf[(jj0 + 1) * 68 + e] = h1v;
            sbuf[(jj0 + 2) * 68 + e] = h2v;
            sbuf[(jj0 + 3) * 68 + e] = h3;
        }
        // we2 chunk: float4
#pragma unroll
        for (int k = 0; k < 4; k++) {
            int q = t + k * 256;
            int jj = q >> 4, vq = (q & 15) * 4;
            *(float4*)(sbuf + 4352 + jj * 64 + vq) =
                *(const float4*)(we2 + (uc * 64 + jj) * 64 + vq);
        }
        __syncthreads();
#pragma unroll 8
        for (int jj = 0; jj < 64; jj++) {
            u64 h01, h23;
            asm("ld.shared.v2.u64 {%0,%1},[%2];"
                : "=l"(h01), "=l"(h23) : "r"(h1base + jj * 272));
            float4 w4 = *(float4*)(sbuf + 4352 + jj * 64 + v0);
            u64 wx = pack2(w4.x, w4.x), wy = pack2(w4.y, w4.y);
            u64 wz = pack2(w4.z, w4.z), ww = pack2(w4.w, w4.w);
            ffma2(acc01[0], h01, wx); ffma2(acc23[0], h23, wx);
            ffma2(acc01[1], h01, wy); ffma2(acc23[1], h23, wy);
            ffma2(acc01[2], h01, wz); ffma2(acc23[2], h23, wz);
            ffma2(acc01[3], h01, ww); ffma2(acc23[3], h23, ww);
        }
        __syncthreads();
    }

    // h2 = relu(acc) -> sbuf flat [e*64+v]
#pragma unroll
    for (int cq = 0; cq < 4; cq++) {
        float lo, hi;
        unpack2(acc01[cq], lo, hi);
        sbuf[(e0 + 0) * 64 + v0 + cq] = fmaxf(lo, 0.f);
        sbuf[(e0 + 1) * 64 + v0 + cq] = fmaxf(hi, 0.f);
        unpack2(acc23[cq], lo, hi);
        sbuf[(e0 + 2) * 64 + v0 + cq] = fmaxf(lo, 0.f);
        sbuf[(e0 + 3) * 64 + v0 + cq] = fmaxf(hi, 0.f);
    }
    __syncthreads();

    // ---- layer3 (vectorized) + higher_pri ----
    if (t < 192) {
        int e = t / 3, w = t - e * 3;
        float a = be3[w];
#pragma unroll
        for (int vq = 0; vq < 64; vq += 4) {
            float4 h4 = *(float4*)(sbuf + e * 64 + vq);
            float4 w4 = *(float4*)(s_we3t + w * 64 + vq);
            a += h4.x * w4.x + h4.y * w4.y + h4.z * w4.z + h4.w * w4.w;
        }
        float sg = 1.f / (1.f + expf(-a));
        s_e4[e * 4 + w] = sg;
        int ge = base + e;
        if (ge < E_TOT) edge_out[ge * 4 + w] = sg;
    } else {
        int e = t - 192;
        int ge = base + e;
        float hp = 0.f;
        if (ge < E_TOT) hp = (pri[s_src[e]] > pri[s_dst[e]]) ? 1.f : 0.f;
        s_e4[e * 4 + 3] = hp;
        if (ge < E_TOT) edge_out[ge * 4 + 3] = hp;
    }
    __syncthreads();

    // ---- heh = relu(e4 @ wp1 + bp1) -> sbuf[e*132+h] ; stage Gt rows ----
    {
        int h = t & 127, eg = t >> 7;
        float w0 = wp1[h], w1v = wp1[128 + h], w2v = wp1[256 + h], w3v = wp1[384 + h];
        float b = bp1[h];
#pragma unroll 4
        for (int s = 0; s < 32; s++) {
            int e = eg * 32 + s;
            float a = b + s_e4[e * 4 + 0] * w0 + s_e4[e * 4 + 1] * w1v
                        + s_e4[e * 4 + 2] * w2v + s_e4[e * 4 + 3] * w3v;
            sbuf[e * 132 + h] = fmaxf(a, 0.f);
        }
    }
    {   // s_G staging, float4 (Gt layout [o*128+h])
        int idx0 = t * 4;
        int row = (idx0 < 512) ? src0 : src1;
        *(float4*)(s_G + idx0) = *(const float4*)(g_Gt + row * 512 + (idx0 & 511));
    }
    __syncthreads();

    // ---- msg[e,o] = sum_h heh[e,h]*Gt[src][o*128+h] + c[src,o]  (float4) ----
    {
        int e = t >> 2, o = t & 3;
        int ge = base + e;
        if (ge < E_TOT) {
            int src = s_src[e];
            int roff = ((src == src0) ? 0 : 512) + o * 128;
            float a = g_c[src * 4 + o];
            const float* hp = sbuf + e * 132;
            const float* gp = s_G + roff;
#pragma unroll
            for (int h = 0; h < 128; h += 4) {
                float4 h4 = *(const float4*)(hp + h);
                float4 g4 = *(const float4*)(gp + h);
                a += h4.x * g4.x + h4.y * g4.y + h4.z * g4.z + h4.w * g4.w;
            }
            g_msg[ge * 4 + o] = a;
        }
    }
}

// ======== K7: final aggregate + root head ========
__global__ void k_final(const float* __restrict__ rootb, float* __restrict__ out) {
    __shared__ float red[256 * 4];
    int j = blockIdx.x, t = threadIdx.x;
    float a[4] = {0.f, 0.f, 0.f, 0.f};
    if (t < N_NODES && t != j) {
        int i = t;
        int pos = (j < i) ? j : j - 1;
        int e = i * NM1 + pos;
        float4 m = *(const float4*)(g_msg + e * 4);
        a[0] = m.x; a[1] = m.y; a[2] = m.z; a[3] = m.w;
    }
#pragma unroll
    for (int q = 0; q < 4; q++) red[t * 4 + q] = a[q];
    __syncthreads();
    for (int s = 128; s > 0; s >>= 1) {
        if (t < s)
#pragma unroll
            for (int q = 0; q < 4; q++) red[t * 4 + q] += red[(t + s) * 4 + q];
        __syncthreads();
    }
    if (t < 4) out[j * 4 + t] = red[t] + g_P[j * 4 + t] + rootb[t];
}

// ---------------- launcher ----------------
extern "C" void kernel_launch(void* const* d_in, const int* in_sizes, int n_in,
                              void* d_out, int out_size) {
    const float* roi   = (const float*)d_in[0];
    const float* bbox  = (const float*)d_in[1];
    const float* dirs  = (const float*)d_in[2];
    const float* pri   = (const float*)d_in[3];
    const float* w1    = (const float*)d_in[4];
    const float* b1    = (const float*)d_in[5];
    const float* w2    = (const float*)d_in[6];
    const float* b2    = (const float*)d_in[7];
    const float* w3    = (const float*)d_in[8];
    const float* b3    = (const float*)d_in[9];
    const float* wi    = (const float*)d_in[10];
    const float* bi    = (const float*)d_in[11];
    const float* we1   = (const float*)d_in[12];
    const float* be1   = (const float*)d_in[13];
    const float* we2   = (const float*)d_in[14];
    const float* be2   = (const float*)d_in[15];
    const float* we3   = (const float*)d_in[16];
    const float* be3   = (const float*)d_in[17];
    const float* wp1   = (const float*)d_in[18];
    const float* bp1   = (const float*)d_in[19];
    const float* wp2   = (const float*)d_in[20];
    const float* bp2   = (const float*)d_in[21];
    const float* rootw = (const float*)d_in[22];
    const float* rootb = (const float*)d_in[23];
    float* out = (float*)d_out;

    k_p0<<<3341, 256>>>(roi, w1, w3, b3, wp2, bp2, wi, rootw, bbox, dirs, we1, be1);
    k_p1<<<672, 256>>>(b1);
    k_p2<<<722, 256>>>(w2);
    k_p3<<<200, 256>>>(b2);
    k_p4<<<252, 256>>>(bi, out + 800);
    k_edge<<<(E_TOT + 63) / 64, 256>>>(pri, we2, be2, we3, be3, wp1, bp1, out + 1600);
    k_final<<<N_NODES, 256>>>(rootb, out);
}